// round 17
// baseline (speedup 1.0000x reference)
#include <cuda_runtime.h>
#include <cuda_bf16.h>
#include <math.h>

#define B_ 2
#define T_ 2048
#define E_ 1024
#define H_ 16
#define D_ 64

// ---------------- device scratch (allocation-free rule) ----------------
__device__ __nv_bfloat16 g_qh[B_ * T_ * E_];
__device__ __nv_bfloat16 g_ql[B_ * T_ * E_];
__device__ __nv_bfloat16 g_Wqh[E_ * 3 * E_];
__device__ __nv_bfloat16 g_Wql[E_ * 3 * E_];
__device__ __nv_bfloat16 g_Woh[E_ * E_];
__device__ __nv_bfloat16 g_Wol[E_ * E_];
__device__ __nv_bfloat16 g_Qh[B_ * H_ * T_ * D_];
__device__ __nv_bfloat16 g_Ql[B_ * H_ * T_ * D_];
__device__ __nv_bfloat16 g_Kh[B_ * H_ * T_ * D_];
__device__ __nv_bfloat16 g_Kl[B_ * H_ * T_ * D_];
__device__ __nv_bfloat16 g_Vh[B_ * H_ * T_ * D_];
__device__ __nv_bfloat16 g_Vl[B_ * H_ * T_ * D_];
__device__ __nv_bfloat16 g_CTXh[B_ * T_ * E_];
__device__ __nv_bfloat16 g_CTXl[B_ * T_ * E_];

// ---------------- helpers ----------------
__device__ __forceinline__ unsigned pk(float lo, float hi) {
  unsigned r;
  asm("cvt.rn.bf16x2.f32 %0, %1, %2;" : "=r"(r) : "f"(hi), "f"(lo));
  return r;
}
__device__ __forceinline__ float blo(unsigned p) { return __uint_as_float(p << 16); }
__device__ __forceinline__ float bhi(unsigned p) { return __uint_as_float(p & 0xffff0000u); }

__device__ __forceinline__ float fexp(float x) {
  float t = fmaf(x, 1.4426950408889634f, 12582912.0f);
  float n = t - 12582912.0f;
  float f = fmaf(x, 1.4426950408889634f, -n);
  float p = 1.3333558146e-3f;
  p = fmaf(p, f, 9.6181291076e-3f);
  p = fmaf(p, f, 5.5504108666e-2f);
  p = fmaf(p, f, 2.4022650696e-1f);
  p = fmaf(p, f, 6.9314718056e-1f);
  p = fmaf(p, f, 1.0f);
  int e = (int)n;
  return p * __int_as_float((e + 127) << 23);
}

__device__ __forceinline__ void ldsm4(unsigned &r0, unsigned &r1, unsigned &r2,
                                      unsigned &r3, unsigned a) {
  asm volatile("ldmatrix.sync.aligned.m8n8.x4.shared.b16 {%0,%1,%2,%3}, [%4];"
               : "=r"(r0), "=r"(r1), "=r"(r2), "=r"(r3) : "r"(a));
}
__device__ __forceinline__ void ldsm4t(unsigned &r0, unsigned &r1, unsigned &r2,
                                       unsigned &r3, unsigned a) {
  asm volatile(
      "ldmatrix.sync.aligned.m8n8.x4.trans.shared.b16 {%0,%1,%2,%3}, [%4];"
      : "=r"(r0), "=r"(r1), "=r"(r2), "=r"(r3) : "r"(a));
}
__device__ __forceinline__ void ldsm2(unsigned &r0, unsigned &r1, unsigned a) {
  asm volatile("ldmatrix.sync.aligned.m8n8.x2.shared.b16 {%0,%1}, [%2];"
               : "=r"(r0), "=r"(r1) : "r"(a));
}
__device__ __forceinline__ void ldsm2t(unsigned &r0, unsigned &r1, unsigned a) {
  asm volatile("ldmatrix.sync.aligned.m8n8.x2.trans.shared.b16 {%0,%1}, [%2];"
               : "=r"(r0), "=r"(r1) : "r"(a));
}
__device__ __forceinline__ void mma16816(float c[4], const unsigned a[4],
                                         unsigned b0, unsigned b1) {
  asm volatile(
      "mma.sync.aligned.m16n8k16.row.col.f32.bf16.bf16.f32 "
      "{%0,%1,%2,%3}, {%4,%5,%6,%7}, {%8,%9}, {%0,%1,%2,%3};"
      : "+f"(c[0]), "+f"(c[1]), "+f"(c[2]), "+f"(c[3])
      : "r"(a[0]), "r"(a[1]), "r"(a[2]), "r"(a[3]), "r"(b0), "r"(b1));
}
__device__ __forceinline__ void cpasync16(unsigned dst, const void* src) {
  asm volatile("cp.async.cg.shared.global [%0], [%1], 16;" :: "r"(dst), "l"(src));
}
__device__ __forceinline__ void cpcommit() {
  asm volatile("cp.async.commit_group;");
}

// ---------------------------------------------------------------------------
// split fp32 -> (hi, lo) bf16 device-symbol planes (0: q, 1: Wqkv, 2: Wout)
// ---------------------------------------------------------------------------
__global__ __launch_bounds__(256) void split_f32(
    const float* __restrict__ src, int which, int n4) {
  int i = blockIdx.x * blockDim.x + threadIdx.x;
  if (i >= n4) return;
  __nv_bfloat16* hi = (which == 0) ? g_qh : ((which == 1) ? g_Wqh : g_Woh);
  __nv_bfloat16* lo = (which == 0) ? g_ql : ((which == 1) ? g_Wql : g_Wol);
  float4 v = ((const float4*)src)[i];
  unsigned h01 = pk(v.x, v.y), h23 = pk(v.z, v.w);
  unsigned l01 = pk(v.x - blo(h01), v.y - bhi(h01));
  unsigned l23 = pk(v.z - blo(h23), v.w - bhi(h23));
  ((uint2*)hi)[i] = make_uint2(h01, h23);
  ((uint2*)lo)[i] = make_uint2(l01, l23);
}

// ---------------------------------------------------------------------------
// GEMM stage loader (BK=32, CTA tile 128x64). Stage layout (24576 B):
//   +0      Ah 128x32 (64B rows, swz ch^((r>>1)&3))   8KB
//   +8192   Al                                        8KB
//   +16384  Bh 32x64  (128B rows, swz ch^(r&7))       4KB
//   +20480  Bl                                        4KB
// ---------------------------------------------------------------------------
__device__ __forceinline__ void gemm_load_stage(
    unsigned base, const __nv_bfloat16* Ah, const __nv_bfloat16* Al,
    const __nv_bfloat16* Bh, const __nv_bfloat16* Bl, int m0, int n0, int k0,
    int lda, int ldb, int tid) {
#pragma unroll
  for (int it = 0; it < 2; it++) {
    int cid = tid + it * 256;
    int r = cid >> 2, ch = cid & 3;
    size_t so = (size_t)(m0 + r) * lda + k0 + ch * 8;
    unsigned dof = base + r * 64 + (((unsigned)(ch ^ ((r >> 1) & 3))) << 4);
    cpasync16(dof, Ah + so);
    cpasync16(dof + 8192, Al + so);
  }
  {
    int r = tid >> 3, ch = tid & 7;
    size_t so = (size_t)(k0 + r) * ldb + n0 + ch * 8;
    unsigned dof = base + 16384 + r * 128 + (((unsigned)(ch ^ (r & 7))) << 4);
    cpasync16(dof, Bh + so);
    cpasync16(dof + 4096, Bl + so);
  }
  cpcommit();
}

// ---------------------------------------------------------------------------
// TC GEMM body: C[128x64]/CTA, BK=32, 2-stage cp.async, 8 warps (4M x 2N).
// 3 MMAs per product (hh + hl + lh). Epilogue via __VA_ARGS__.
// ---------------------------------------------------------------------------
#define GEMM_TC_BODY(LDA, LDB, ...)                                             \
  extern __shared__ unsigned char SMD[];                                        \
  int tid = threadIdx.x, lane = tid & 31, w = tid >> 5;                         \
  int wm = w >> 1, wn = w & 1;                                                  \
  int m0 = blockIdx.y * 128, n0 = blockIdx.x * 64;                              \
  unsigned bSM = (unsigned)__cvta_generic_to_shared(SMD);                       \
  float acc[2][4][4];                                                           \
  _Pragma("unroll") for (int mf = 0; mf < 2; mf++)                              \
    _Pragma("unroll") for (int nf = 0; nf < 4; nf++)                            \
      _Pragma("unroll") for (int j = 0; j < 4; j++) acc[mf][nf][j] = 0.f;       \
  gemm_load_stage(bSM, Ah, Al, Bh, Bl, m0, n0, 0, (LDA), (LDB), tid);           \
  for (int ki = 0; ki < 32; ki++) {                                             \
    if (ki + 1 < 32) {                                                          \
      gemm_load_stage(bSM + ((ki + 1) & 1) * 24576, Ah, Al, Bh, Bl, m0, n0,     \
                      (ki + 1) * 32, (LDA), (LDB), tid);                        \
      asm volatile("cp.async.wait_group 1;");                                   \
    } else {                                                                    \
      asm volatile("cp.async.wait_group 0;");                                   \
    }                                                                           \
    __syncthreads();                                                            \
    unsigned sA = bSM + (ki & 1) * 24576;                                       \
    unsigned sB = sA + 16384;                                                   \
    _Pragma("unroll") for (int kc = 0; kc < 2; kc++) {                          \
      unsigned ah[2][4];                                                        \
      unsigned al[2][4];                                                        \
      _Pragma("unroll") for (int mf = 0; mf < 2; mf++) {                        \
        int row = wm * 32 + mf * 16 + (lane & 15);                              \
        int ch = kc * 2 + (lane >> 4);                                          \
        unsigned off = row * 64 + (((unsigned)(ch ^ ((row >> 1) & 3))) << 4);   \
        ldsm4(ah[mf][0], ah[mf][1], ah[mf][2], ah[mf][3], sA + off);            \
        ldsm4(al[mf][0], al[mf][1], al[mf][2], al[mf][3], sA + 8192 + off);     \
      }                                                                         \
      int brow = kc * 16 + ((lane >> 3) & 1) * 8 + (lane & 7);                  \
      _Pragma("unroll") for (int nfp = 0; nfp < 2; nfp++) {                     \
        int ch = wn * 4 + nfp * 2 + (lane >> 4);                                \
        unsigned off = brow * 128 + (((unsigned)(ch ^ (brow & 7))) << 4);       \
        unsigned bh[4];                                                         \
        unsigned bl[4];                                                         \
        ldsm4t(bh[0], bh[1], bh[2], bh[3], sB + off);                           \
        ldsm4t(bl[0], bl[1], bl[2], bl[3], sB + 4096 + off);                    \
        _Pragma("unroll") for (int s = 0; s < 2; s++) {                         \
          _Pragma("unroll") for (int mf = 0; mf < 2; mf++) {                    \
            mma16816(acc[mf][nfp * 2 + s], ah[mf], bh[s * 2], bh[s * 2 + 1]);   \
            mma16816(acc[mf][nfp * 2 + s], ah[mf], bl[s * 2], bl[s * 2 + 1]);   \
            mma16816(acc[mf][nfp * 2 + s], al[mf], bh[s * 2], bh[s * 2 + 1]);   \
          }                                                                     \
        }                                                                       \
      }                                                                         \
    }                                                                           \
    __syncthreads();                                                            \
  }                                                                             \
  int g = lane >> 2, tig = lane & 3;                                            \
  __VA_ARGS__

// ---- GEMM1: qkv projection, scatter-split to Q/K/V planes ----
__global__ __launch_bounds__(256, 2) void gemm_qkv_tc(
    const float* __restrict__ bias) {
  const __nv_bfloat16* Ah = g_qh;
  const __nv_bfloat16* Al = g_ql;
  const __nv_bfloat16* Bh = g_Wqh;
  const __nv_bfloat16* Bl = g_Wql;
  GEMM_TC_BODY(E_, 3 * E_, {
#pragma unroll
    for (int mf = 0; mf < 2; mf++) {
#pragma unroll
      for (int nf = 0; nf < 4; nf++) {
        int j = n0 + wn * 32 + nf * 8 + 2 * tig;
        int sel = j >> 10;
        int e = j & 1023;
        int hh = e >> 6;
        int d = e & 63;
        float bs0 = bias[j];
        float bs1 = bias[j + 1];
        float sc = (sel == 0) ? 0.125f : 1.0f;
        __nv_bfloat16* dh = (sel == 0) ? g_Qh : ((sel == 1) ? g_Kh : g_Vh);
        __nv_bfloat16* dl = (sel == 0) ? g_Ql : ((sel == 1) ? g_Kl : g_Vl);
#pragma unroll
        for (int half = 0; half < 2; half++) {
          int r = m0 + wm * 32 + mf * 16 + g + half * 8;
          int bb = r >> 11;
          int t = r & (T_ - 1);
          float v0 = (acc[mf][nf][half * 2 + 0] + bs0) * sc;
          float v1 = (acc[mf][nf][half * 2 + 1] + bs1) * sc;
          unsigned h01 = pk(v0, v1);
          unsigned l01 = pk(v0 - blo(h01), v1 - bhi(h01));
          size_t idx = ((size_t)(bb * H_ + hh) * T_ + t) * D_ + d;
          *(unsigned*)&dh[idx] = h01;
          *(unsigned*)&dl[idx] = l01;
        }
      }
    }
  })
}

// ---- GEMM2: out = CTX @ Wout + bout (fp32 result) ----
__global__ __launch_bounds__(256, 2) void gemm_out_tc(
    const float* __restrict__ bias, float* __restrict__ out) {
  const __nv_bfloat16* Ah = g_CTXh;
  const __nv_bfloat16* Al = g_CTXl;
  const __nv_bfloat16* Bh = g_Woh;
  const __nv_bfloat16* Bl = g_Wol;
  GEMM_TC_BODY(E_, E_, {
#pragma unroll
    for (int mf = 0; mf < 2; mf++) {
#pragma unroll
      for (int nf = 0; nf < 4; nf++) {
        int j = n0 + wn * 32 + nf * 8 + 2 * tig;
        float bs0 = bias[j];
        float bs1 = bias[j + 1];
#pragma unroll
        for (int half = 0; half < 2; half++) {
          int r = m0 + wm * 32 + mf * 16 + g + half * 8;
          float2 v;
          v.x = acc[mf][nf][half * 2 + 0] + bs0;
          v.y = acc[mf][nf][half * 2 + 1] + bs1;
          *(float2*)&out[(size_t)r * E_ + j] = v;
        }
      }
    }
  })
}

// ---------------------------------------------------------------------------
// Two-pass tensor-core attention, 128-row q-tile, warp = 16 rows x 64 keys.
// Pass 1: S (3-MMA split) + exp -> per-row sums (K planes only staged).
// Pass 2: identical S recompute (bitwise), write NORMALIZED P to attn_out,
// accumulate O with normalized P, write CTX split planes directly.
// No separate scale kernel, no cross-warp reductions.
// Smem: stage s at s*32768 (Kh+0, Kl+8192, Vh+16384, Vl+24576); mask at 65536.
// Q staged once in stage0 area (Qh@0, Ql@16384) before the pipeline starts.
// ---------------------------------------------------------------------------
__device__ __forceinline__ void attn_plane_async(unsigned dst,
                                                 const __nv_bfloat16* src,
                                                 int row0, int tid) {
#pragma unroll
  for (int it = 0; it < 2; it++) {
    int cid = tid + it * 256;
    int r = cid >> 3, ch = cid & 7;
    cpasync16(dst + r * 128 + (((unsigned)(ch ^ (r & 7))) << 4),
              src + (size_t)(row0 + r) * D_ + ch * 8);
  }
}

__global__ __launch_bounds__(256) void attn_kernel(
    const int* __restrict__ mask, float* __restrict__ attn_out) {
  extern __shared__ __align__(16) unsigned char ASM[];
  unsigned char* mS = ASM + 65536;

  int tid = threadIdx.x;
  int lane = tid & 31, w = tid >> 5;
  int g = lane >> 2, tig = lane & 3;
  int qt = blockIdx.x, h = blockIdx.y, b = blockIdx.z;
  int q0 = qt * 128;
  size_t hb = (size_t)(b * H_ + h) * T_;

  const __nv_bfloat16* Qhg = g_Qh + hb * D_;
  const __nv_bfloat16* Qlg = g_Ql + hb * D_;
  const __nv_bfloat16* Khg = g_Kh + hb * D_;
  const __nv_bfloat16* Klg = g_Kl + hb * D_;
  const __nv_bfloat16* Vhg = g_Vh + hb * D_;
  const __nv_bfloat16* Vlg = g_Vl + hb * D_;

  unsigned bASM = (unsigned)__cvta_generic_to_shared(ASM);

  for (int i = tid; i < T_; i += 256) mS[i] = (mask[b * T_ + i] != 0) ? 1 : 0;

  // ---- stage Q (128 rows, hi@0 lo@16384), load frags, free the area ----
#pragma unroll
  for (int it = 0; it < 4; it++) {
    int cid = tid + it * 256;
    int r = cid >> 3, ch = cid & 7;
    unsigned dof = r * 128 + ((ch ^ (r & 7)) << 4);
    *(uint4*)(ASM + dof) = *(const uint4*)(Qhg + (size_t)(q0 + r) * D_ + ch * 8);
    *(uint4*)(ASM + 16384 + dof) =
        *(const uint4*)(Qlg + (size_t)(q0 + r) * D_ + ch * 8);
  }
  __syncthreads();
  unsigned qh[4][4], ql[4][4];
  {
    int ar = w * 16 + (lane & 15);
    int chb = lane >> 4;
#pragma unroll
    for (int kc = 0; kc < 4; kc++) {
      int ch = kc * 2 + chb;
      unsigned off = ar * 128 + ((ch ^ (ar & 7)) << 4);
      ldsm4(qh[kc][0], qh[kc][1], qh[kc][2], qh[kc][3], bASM + off);
      ldsm4(ql[kc][0], ql[kc][1], ql[kc][2], ql[kc][3], bASM + 16384 + off);
    }
  }
  __syncthreads();

  const int row_q = q0 + w * 16 + g;
  const int NT = T_ / 64;
  const int kb = lane & 7;
  const int cb = (lane >> 3) & 1;

  // ================= PASS 1: row sums (K planes only) =================
  float l0 = 0.f, l8 = 0.f;
  attn_plane_async(bASM + 0, Khg, 0, tid);
  attn_plane_async(bASM + 8192, Klg, 0, tid);
  cpcommit();
  for (int kt = 0; kt < NT; kt++) {
    int k0 = kt * 64;
    if (kt + 1 < NT) {
      unsigned nb = bASM + ((kt + 1) & 1) * 32768;
      attn_plane_async(nb + 0, Khg, (kt + 1) * 64, tid);
      attn_plane_async(nb + 8192, Klg, (kt + 1) * 64, tid);
      cpcommit();
      asm volatile("cp.async.wait_group 1;");
    } else {
      asm volatile("cp.async.wait_group 0;");
    }
    __syncthreads();
    unsigned sKh = bASM + (kt & 1) * 32768;
    unsigned sKl = sKh + 8192;
#pragma unroll
    for (int nc = 0; nc < 8; nc++) {
      float c[4] = {0.f, 0.f, 0.f, 0.f};
      int krow = nc * 8 + kb;
      unsigned rowoff = krow * 128;
      unsigned sw = krow & 7;
#pragma unroll
      for (int kc = 0; kc < 4; kc++) {
        int ch = kc * 2 + cb;
        unsigned off = rowoff + ((ch ^ sw) << 4);
        unsigned bh0, bh1, bl0, bl1;
        ldsm2(bh0, bh1, sKh + off);
        ldsm2(bl0, bl1, sKl + off);
        mma16816(c, qh[kc], bh0, bh1);
        mma16816(c, qh[kc], bl0, bl1);
        mma16816(c, ql[kc], bh0, bh1);
      }
      int col = k0 + nc * 8 + 2 * tig;
      if (!mS[col])     { l0 += fexp(c[0]); l8 += fexp(c[2]); }
      if (!mS[col + 1]) { l0 += fexp(c[1]); l8 += fexp(c[3]); }
    }
    __syncthreads();
  }
  // quad reduce (cols live in tig lanes only)
  l0 += __shfl_xor_sync(0xffffffffu, l0, 1);
  l0 += __shfl_xor_sync(0xffffffffu, l0, 2);
  l8 += __shfl_xor_sync(0xffffffffu, l8, 1);
  l8 += __shfl_xor_sync(0xffffffffu, l8, 2);
  float inv0 = 1.f / l0;
  float inv8 = 1.f / l8;

  // ================= PASS 2: normalized P + O =================
  float o[8][4];
#pragma unroll
  for (int dc = 0; dc < 8; dc++)
#pragma unroll
    for (int j = 0; j < 4; j++) o[dc][j] = 0.f;

  attn_plane_async(bASM + 0, Khg, 0, tid);
  attn_plane_async(bASM + 8192, Klg, 0, tid);
  attn_plane_async(bASM + 16384, Vhg, 0, tid);
  attn_plane_async(bASM + 24576, Vlg, 0, tid);
  cpcommit();
  for (int kt = 0; kt < NT; kt++) {
    int k0 = kt * 64;
    if (kt + 1 < NT) {
      unsigned nb = bASM + ((kt + 1) & 1) * 32768;
      int nk0 = (kt + 1) * 64;
      attn_plane_async(nb + 0, Khg, nk0, tid);
      attn_plane_async(nb + 8192, Klg, nk0, tid);
      attn_plane_async(nb + 16384, Vhg, nk0, tid);
      attn_plane_async(nb + 24576, Vlg, nk0, tid);
      cpcommit();
      asm volatile("cp.async.wait_group 1;");
    } else {
      asm volatile("cp.async.wait_group 0;");
    }
    __syncthreads();
    unsigned sKh = bASM + (kt & 1) * 32768;
    unsigned sKl = sKh + 8192;
    unsigned sVh = sKh + 16384;
    unsigned sVl = sKh + 24576;

#pragma unroll
    for (int kc2 = 0; kc2 < 4; kc2++) {   // 16-key chunks
      unsigned pah[4], pal[4];
#pragma unroll
      for (int hf = 0; hf < 2; hf++) {
        int nc = kc2 * 2 + hf;
        float c[4] = {0.f, 0.f, 0.f, 0.f};
        int krow = nc * 8 + kb;
        unsigned rowoff = krow * 128;
        unsigned sw = krow & 7;
#pragma unroll
        for (int kc = 0; kc < 4; kc++) {
          int ch = kc * 2 + cb;
          unsigned off = rowoff + ((ch ^ sw) << 4);
          unsigned bh0, bh1, bl0, bl1;
          ldsm2(bh0, bh1, sKh + off);
          ldsm2(bl0, bl1, sKl + off);
          mma16816(c, qh[kc], bh0, bh1);
          mma16816(c, qh[kc], bl0, bl1);
          mma16816(c, ql[kc], bh0, bh1);
        }
        int col = k0 + nc * 8 + 2 * tig;
        float p0 = 0.f, p1 = 0.f, p2 = 0.f, p3 = 0.f;
        if (!mS[col])     { p0 = fexp(c[0]) * inv0; p2 = fexp(c[2]) * inv8; }
        if (!mS[col + 1]) { p1 = fexp(c[1]) * inv0; p3 = fexp(c[3]) * inv8; }
        size_t ba = (hb + row_q) * T_ + col;
        *(float2*)&attn_out[ba] = make_float2(p0, p1);
        *(float2*)&attn_out[ba + (size_t)8 * T_] = make_float2(p2, p3);
        unsigned h01 = pk(p0, p1), h23 = pk(p2, p3);
        pah[hf * 2 + 0] = h01;
        pah[hf * 2 + 1] = h23;
        pal[hf * 2 + 0] = pk(p0 - blo(h01), p1 - bhi(h01));
        pal[hf * 2 + 1] = pk(p2 - blo(h23), p3 - bhi(h23));
      }
      // PV for this 16-key chunk
      int vrow = kc2 * 16 + ((lane >> 3) & 1) * 8 + (lane & 7);
      unsigned rowoff = vrow * 128;
      unsigned sw = vrow & 7;
#pragma unroll
      for (int dc = 0; dc < 8; dc++) {
        unsigned off = rowoff + ((dc ^ sw) << 4);
        unsigned bh0, bh1, bl0, bl1;
        ldsm2t(bh0, bh1, sVh + off);
        ldsm2t(bl0, bl1, sVl + off);
        mma16816(o[dc], pah, bh0, bh1);
        mma16816(o[dc], pah, bl0, bl1);
        mma16816(o[dc], pal, bh0, bh1);
      }
    }
    __syncthreads();
  }

  // ---- write CTX split planes (O already normalized) ----
#pragma unroll
  for (int dc = 0; dc < 8; dc++) {
    size_t i0 = ((size_t)(b * T_) + row_q) * E_ + h * 64 + dc * 8 + 2 * tig;
    unsigned h01 = pk(o[dc][0], o[dc][1]);
    unsigned l01 = pk(o[dc][0] - blo(h01), o[dc][1] - bhi(h01));
    *(unsigned*)&g_CTXh[i0] = h01;
    *(unsigned*)&g_CTXl[i0] = l01;
    unsigned h23 = pk(o[dc][2], o[dc][3]);
    unsigned l23 = pk(o[dc][2] - blo(h23), o[dc][3] - bhi(h23));
    *(unsigned*)&g_CTXh[i0 + (size_t)8 * E_] = h23;
    *(unsigned*)&g_CTXl[i0 + (size_t)8 * E_] = l23;
  }
}

// ---------------------------------------------------------------------------
extern "C" void kernel_launch(void* const* d_in, const int* in_sizes, int n_in,
                              void* d_out, int out_size) {
  const float* q = (const float*)d_in[0];
  const int* mask = (const int*)d_in[3];
  const float* Wqkv = (const float*)d_in[4];
  const float* bqkv = (const float*)d_in[5];
  const float* Wout = (const float*)d_in[6];
  const float* bout = (const float*)d_in[7];
  float* out = (float*)d_out;

  const size_t out_elems = (size_t)B_ * T_ * E_;
  float* attn_ptr = out + out_elems;

  dim3 blk(256);

  // 0) split inputs to bf16 hi/lo planes
  int n4q = B_ * T_ * E_ / 4;
  int n4wq = E_ * 3 * E_ / 4;
  int n4wo = E_ * E_ / 4;
  split_f32<<<(n4q + 255) / 256, blk>>>(q, 0, n4q);
  split_f32<<<(n4wq + 255) / 256, blk>>>(Wqkv, 1, n4wq);
  split_f32<<<(n4wo + 255) / 256, blk>>>(Wout, 2, n4wo);

  // 1) QKV projection (BK=32 pipeline, 48KB smem, 2 CTAs/SM)
  cudaFuncSetAttribute(gemm_qkv_tc, cudaFuncAttributeMaxDynamicSharedMemorySize,
                       49152);
  gemm_qkv_tc<<<dim3(3 * E_ / 64, B_ * T_ / 128), blk, 49152>>>(bqkv);

  // 2) Two-pass attention (128-row q tiles, normalized in-kernel; 66KB smem)
  cudaFuncSetAttribute(attn_kernel, cudaFuncAttributeMaxDynamicSharedMemorySize,
                       67584);
  attn_kernel<<<dim3(T_ / 128, H_, B_), blk, 67584>>>(mask, attn_ptr);

  // 3) Output projection (BK=32 pipeline, 2 CTAs/SM)
  cudaFuncSetAttribute(gemm_out_tc, cudaFuncAttributeMaxDynamicSharedMemorySize,
                       49152);
  gemm_out_tc<<<dim3(E_ / 64, B_ * T_ / 128), blk, 49152>>>(bout, out);
}